// round 11
// baseline (speedup 1.0000x reference)
#include <cuda_runtime.h>
#include <cuda_bf16.h>
#include <cstdint>

// Problem constants (shapes fixed by the dataset)
#define DD 128
#define NN 50000
#define EE 600000

// Scratch (no runtime allocation allowed).
__device__ __align__(16) float g_tmp1[NN * DD];   // layer buffers
__device__ __align__(16) float g_tmp2[NN * DD];
__device__ float g_degf[NN];       // weighted in-degree
__device__ int   g_cnt[NN];        // in-degree counts
__device__ int   g_cursor[NN];     // fill cursors
__device__ int   g_off[NN + 1];    // CSR offsets (by destination)
__device__ __align__(8) int2 g_srcw[EE];  // CSR slots: {src row, norm bits}

// ---------------------------------------------------------------------------
// Zero bookkeeping arrays
// ---------------------------------------------------------------------------
__global__ void zero_kernel(int n) {
    int i = blockIdx.x * blockDim.x + threadIdx.x;
    if (i < n) { g_cnt[i] = 0; g_cursor[i] = 0; g_degf[i] = 0.f; }
}

// Per-destination: edge count (int atomic) + weighted degree (float atomic).
// adj is int32 [2, E]: row = adj[e], col = adj[E + e].
__global__ void count_kernel(const int* __restrict__ adj,
                             const float* __restrict__ ew, int E, int N) {
    int e = blockIdx.x * blockDim.x + threadIdx.x;
    if (e < E) {
        int col = adj[E + e];
        if ((unsigned)col < (unsigned)N) {
            atomicAdd(&g_cnt[col], 1);
            atomicAdd(&g_degf[col], ew[e]);
        }
    }
}

// Exclusive scan of cnt[0..N) into off[0..N], single block of 1024 threads.
__global__ __launch_bounds__(1024) void scan_kernel(int N) {
    __shared__ int s[1024];
    const int t = threadIdx.x;
    const int CH = (NN + 1023) / 1024;            // 49
    int base = t * CH;
    int sum = 0;
    for (int i = 0; i < CH; i++) {
        int idx = base + i;
        if (idx < N) sum += g_cnt[idx];
    }
    s[t] = sum;
    __syncthreads();
    for (int d = 1; d < 1024; d <<= 1) {
        int v = (t >= d) ? s[t - d] : 0;
        __syncthreads();
        s[t] += v;
        __syncthreads();
    }
    int start = (t == 0) ? 0 : s[t - 1];
    for (int i = 0; i < CH; i++) {
        int idx = base + i;
        if (idx < N) { g_off[idx] = start; start += g_cnt[idx]; }
    }
    if (t == 1023) g_off[N] = s[1023];
}

// Fill CSR slots directly with {src row, normalized weight}.
// norm = rsqrt(deg[row]) * ew * rsqrt(deg[col]) computed inline — removes the
// eidx->norm indirection from the gather hot loop entirely.
__global__ void fill_kernel(const int* __restrict__ adj,
                            const float* __restrict__ ew, int E, int N) {
    int e = blockIdx.x * blockDim.x + threadIdx.x;
    if (e >= E) return;
    int col = adj[E + e];
    if ((unsigned)col >= (unsigned)N) return;
    int row = adj[e];
    float degr = ((unsigned)row < (unsigned)N) ? g_degf[row] : 0.f;
    float degc = g_degf[col];
    float dr = (degr > 0.f) ? rsqrtf(degr) : 0.f;
    float dc = (degc > 0.f) ? rsqrtf(degc) : 0.f;
    float w = dr * ew[e] * dc;
    int r = ((unsigned)row < (unsigned)N) ? row : 0;   // w==0 if clamped
    int pos = atomicAdd(&g_cursor[col], 1);
    g_srcw[g_off[col] + pos] = make_int2(r, __float_as_int(w));
}

// ---------------------------------------------------------------------------
// GEMM: C[M,128] = A[M,128] @ W[128,128], fp32.
// 64 rows x 128 cols per block, 256 threads, 8x4 register tile per thread.
// ---------------------------------------------------------------------------
__global__ __launch_bounds__(256) void gemm_kernel(
    const float* __restrict__ A, const float* __restrict__ W,
    float* __restrict__ C, int M) {
    __shared__ float xs[64][32];
    __shared__ float ws[32][128];

    int t = threadIdx.x;
    int tx = t & 31;
    int ty = t >> 5;
    int rowBase = blockIdx.x * 64;

    float acc[8][4];
#pragma unroll
    for (int r = 0; r < 8; r++)
#pragma unroll
        for (int c = 0; c < 4; c++) acc[r][c] = 0.f;

#pragma unroll
    for (int kc = 0; kc < 4; kc++) {
#pragma unroll
        for (int j = 0; j < 8; j++) {
            int idx = t + j * 256;
            int r = idx >> 5, k = idx & 31;
            int row = rowBase + r;
            xs[r][k] = (row < M) ? A[row * DD + kc * 32 + k] : 0.f;
        }
#pragma unroll
        for (int j = 0; j < 16; j++) {
            int idx = t + j * 256;
            int k = idx >> 7, c = idx & 127;
            ws[k][c] = W[(kc * 32 + k) * DD + c];
        }
        __syncthreads();

#pragma unroll
        for (int k = 0; k < 32; k++) {
            float4 wv = *(const float4*)&ws[k][tx * 4];
#pragma unroll
            for (int r = 0; r < 8; r++) {
                float a = xs[ty * 8 + r][k];
                acc[r][0] += a * wv.x;
                acc[r][1] += a * wv.y;
                acc[r][2] += a * wv.z;
                acc[r][3] += a * wv.w;
            }
        }
        __syncthreads();
    }

#pragma unroll
    for (int r = 0; r < 8; r++) {
        int row = rowBase + ty * 8 + r;
        if (row < M)
            *(float4*)&C[row * DD + tx * 4] =
                make_float4(acc[r][0], acc[r][1], acc[r][2], acc[r][3]);
    }
}

// ---------------------------------------------------------------------------
// Warp-cooperative CSR gather + fused epilogue. One warp per destination
// node; lane owns 4 features. Metadata for 32 edges is fetched with ONE
// coalesced int2 load per lane, then broadcast via shfl while the (independent)
// 512B row-gathers issue back-to-back — short dependency chain, high MLP.
// ---------------------------------------------------------------------------
template <bool RESID>
__global__ __launch_bounds__(256) void gather_kernel(
    const float* __restrict__ src, const float* __restrict__ bias,
    const float* __restrict__ resid,
    float* __restrict__ dst, int N) {
    int g = blockIdx.x * blockDim.x + threadIdx.x;
    int n = g >> 5, lane = g & 31;
    if (n >= N) return;                 // warp-uniform exit

    const int j0 = g_off[n], j1 = g_off[n + 1];
    const int fo = lane << 2;
    float ax = 0.f, ay = 0.f, az = 0.f, aw = 0.f;

    for (int base = j0; base < j1; base += 32) {
        int jj = base + lane;
        int2 sw = (jj < j1) ? g_srcw[jj] : make_int2(0, 0);
        int cnt = min(32, j1 - base);
        for (int i = 0; i < cnt; i++) {
            int   r = __shfl_sync(0xFFFFFFFFu, sw.x, i);
            float w = __int_as_float(__shfl_sync(0xFFFFFFFFu, sw.y, i));
            float4 v = *(const float4*)(src + (size_t)r * DD + fo);
            ax += w * v.x; ay += w * v.y; az += w * v.z; aw += w * v.w;
        }
    }

    float4 b = *(const float4*)(bias + fo);
    ax = fmaxf(ax + b.x, 0.f);
    ay = fmaxf(ay + b.y, 0.f);
    az = fmaxf(az + b.z, 0.f);
    aw = fmaxf(aw + b.w, 0.f);
    if (RESID) {
        float4 rv = *(const float4*)(resid + (size_t)n * DD + fo);
        ax += rv.x; ay += rv.y; az += rv.z; aw += rv.w;
    }
    *(float4*)(dst + (size_t)n * DD + fo) = make_float4(ax, ay, az, aw);
}

// ---------------------------------------------------------------------------
extern "C" void kernel_launch(void* const* d_in, const int* in_sizes, int n_in,
                              void* d_out, int out_size) {
    const float* x   = (const float*)d_in[0];
    const int*   adj = (const int*)d_in[1];     // int32 [2, E]
    const float* ew  = (const float*)d_in[2];
    const float* W1  = (const float*)d_in[3];
    const float* b1  = (const float*)d_in[4];
    const float* W2  = (const float*)d_in[5];
    const float* b2  = (const float*)d_in[6];
    float*       out = (float*)d_out;

    const int E = in_sizes[2];           // 600000
    const int N = in_sizes[0] / DD;      // 50000

    const int TB = 256;
    dim3 blkE((E + TB - 1) / TB);
    dim3 blkN((N + TB - 1) / TB);
    dim3 blkW((N * 32 + TB - 1) / TB);   // warp-per-node
    dim3 blkG((N + 63) / 64);

    // CSR build interleaved with GEMM1 so the ncu capture slot (4th launch)
    // lands on gemm_kernel for diagnosis.
    zero_kernel<<<blkN, TB>>>(N);                       // 1
    count_kernel<<<blkE, TB>>>(adj, ew, E, N);          // 2
    scan_kernel<<<1, 1024>>>(N);                        // 3
    gemm_kernel<<<blkG, TB>>>(x, W1, g_tmp1, N);        // 4  <- profiled
    fill_kernel<<<blkE, TB>>>(adj, ew, E, N);           // 5

    // Layer 1 aggregate: tmp2 = relu(gather(tmp1) + b1)
    gather_kernel<false><<<blkW, TB>>>(g_tmp1, b1, nullptr, g_tmp2, N);  // 6

    // Layer 2: tmp1 = tmp2@W2 ; out = relu(gather(tmp1) + b2) + x
    gemm_kernel<<<blkG, TB>>>(g_tmp2, W2, g_tmp1, N);                    // 7
    gather_kernel<true><<<blkW, TB>>>(g_tmp1, b2, x, out, N);            // 8
}

// round 16
// speedup vs baseline: 17.2147x; 17.2147x over previous
#include <cuda_runtime.h>
#include <cuda_bf16.h>
#include <cstdint>

// Problem constants (shapes fixed by the dataset)
#define DD 128
#define NN 50000
#define EE 600000

// Scratch (no runtime allocation allowed).
// NOTE: these may ONLY be touched from device code, or via real device
// addresses obtained with cudaGetSymbolAddress. Passing the symbol itself as
// a kernel argument from host code hands the kernel the HOST shadow address —
// which GB300's ATS happily services over NVLink-C2C at 200 GB/s (the R10/R11
// 3.6 ms mystery).
__device__ __align__(16) float g_tmp1[NN * DD];   // layer buffers
__device__ __align__(16) float g_tmp2[NN * DD];
__device__ float g_degf[NN];       // weighted in-degree
__device__ int   g_cnt[NN];        // in-degree counts
__device__ int   g_cursor[NN];     // fill cursors
__device__ int   g_off[NN + 1];    // CSR offsets (by destination)
__device__ __align__(8) int2 g_srcw[EE];  // CSR slots: {src row, norm bits}

// ---------------------------------------------------------------------------
// Zero bookkeeping arrays
// ---------------------------------------------------------------------------
__global__ void zero_kernel(int n) {
    int i = blockIdx.x * blockDim.x + threadIdx.x;
    if (i < n) { g_cnt[i] = 0; g_cursor[i] = 0; g_degf[i] = 0.f; }
}

// Per-destination: edge count (int atomic) + weighted degree (float atomic).
// adj is int32 [2, E]: row = adj[e], col = adj[E + e].
__global__ void count_kernel(const int* __restrict__ adj,
                             const float* __restrict__ ew, int E, int N) {
    int e = blockIdx.x * blockDim.x + threadIdx.x;
    if (e < E) {
        int col = adj[E + e];
        if ((unsigned)col < (unsigned)N) {
            atomicAdd(&g_cnt[col], 1);
            atomicAdd(&g_degf[col], ew[e]);
        }
    }
}

// Exclusive scan of cnt[0..N) into off[0..N], single block of 1024 threads.
__global__ __launch_bounds__(1024) void scan_kernel(int N) {
    __shared__ int s[1024];
    const int t = threadIdx.x;
    const int CH = (NN + 1023) / 1024;            // 49
    int base = t * CH;
    int sum = 0;
    for (int i = 0; i < CH; i++) {
        int idx = base + i;
        if (idx < N) sum += g_cnt[idx];
    }
    s[t] = sum;
    __syncthreads();
    for (int d = 1; d < 1024; d <<= 1) {
        int v = (t >= d) ? s[t - d] : 0;
        __syncthreads();
        s[t] += v;
        __syncthreads();
    }
    int start = (t == 0) ? 0 : s[t - 1];
    for (int i = 0; i < CH; i++) {
        int idx = base + i;
        if (idx < N) { g_off[idx] = start; start += g_cnt[idx]; }
    }
    if (t == 1023) g_off[N] = s[1023];
}

// Fill CSR slots directly with {src row, normalized weight}.
__global__ void fill_kernel(const int* __restrict__ adj,
                            const float* __restrict__ ew, int E, int N) {
    int e = blockIdx.x * blockDim.x + threadIdx.x;
    if (e >= E) return;
    int col = adj[E + e];
    if ((unsigned)col >= (unsigned)N) return;
    int row = adj[e];
    float degr = ((unsigned)row < (unsigned)N) ? g_degf[row] : 0.f;
    float degc = g_degf[col];
    float dr = (degr > 0.f) ? rsqrtf(degr) : 0.f;
    float dc = (degc > 0.f) ? rsqrtf(degc) : 0.f;
    float w = dr * ew[e] * dc;
    int r = ((unsigned)row < (unsigned)N) ? row : 0;   // w==0 if clamped
    int pos = atomicAdd(&g_cursor[col], 1);
    g_srcw[g_off[col] + pos] = make_int2(r, __float_as_int(w));
}

// ---------------------------------------------------------------------------
// GEMM: C[M,128] = A[M,128] @ W[128,128], fp32.
// 64 rows x 128 cols per block, 256 threads, 8x4 register tile per thread.
// ---------------------------------------------------------------------------
__global__ __launch_bounds__(256) void gemm_kernel(
    const float* __restrict__ A, const float* __restrict__ W,
    float* __restrict__ C, int M) {
    __shared__ float xs[64][32];
    __shared__ float ws[32][128];

    int t = threadIdx.x;
    int tx = t & 31;
    int ty = t >> 5;
    int rowBase = blockIdx.x * 64;

    float acc[8][4];
#pragma unroll
    for (int r = 0; r < 8; r++)
#pragma unroll
        for (int c = 0; c < 4; c++) acc[r][c] = 0.f;

#pragma unroll
    for (int kc = 0; kc < 4; kc++) {
#pragma unroll
        for (int j = 0; j < 8; j++) {
            int idx = t + j * 256;
            int r = idx >> 5, k = idx & 31;
            int row = rowBase + r;
            xs[r][k] = (row < M) ? A[row * DD + kc * 32 + k] : 0.f;
        }
#pragma unroll
        for (int j = 0; j < 16; j++) {
            int idx = t + j * 256;
            int k = idx >> 7, c = idx & 127;
            ws[k][c] = W[(kc * 32 + k) * DD + c];
        }
        __syncthreads();

#pragma unroll
        for (int k = 0; k < 32; k++) {
            float4 wv = *(const float4*)&ws[k][tx * 4];
#pragma unroll
            for (int r = 0; r < 8; r++) {
                float a = xs[ty * 8 + r][k];
                acc[r][0] += a * wv.x;
                acc[r][1] += a * wv.y;
                acc[r][2] += a * wv.z;
                acc[r][3] += a * wv.w;
            }
        }
        __syncthreads();
    }

#pragma unroll
    for (int r = 0; r < 8; r++) {
        int row = rowBase + ty * 8 + r;
        if (row < M)
            *(float4*)&C[row * DD + tx * 4] =
                make_float4(acc[r][0], acc[r][1], acc[r][2], acc[r][3]);
    }
}

// ---------------------------------------------------------------------------
// Warp-cooperative CSR gather + fused epilogue. One warp per destination
// node; lane owns 4 features. One coalesced int2 metadata load covers 32
// edges; rows broadcast via shfl while independent 512B row-gathers issue.
// ---------------------------------------------------------------------------
template <bool RESID>
__global__ __launch_bounds__(256) void gather_kernel(
    const float* __restrict__ src, const float* __restrict__ bias,
    const float* __restrict__ resid,
    float* __restrict__ dst, int N) {
    int g = blockIdx.x * blockDim.x + threadIdx.x;
    int n = g >> 5, lane = g & 31;
    if (n >= N) return;                 // warp-uniform exit (grid is exact)

    const int j0 = g_off[n], j1 = g_off[n + 1];
    const int fo = lane << 2;
    float ax = 0.f, ay = 0.f, az = 0.f, aw = 0.f;

    for (int base = j0; base < j1; base += 32) {
        int jj = base + lane;
        int2 sw = (jj < j1) ? g_srcw[jj] : make_int2(0, 0);
        int cnt = min(32, j1 - base);
#pragma unroll 4
        for (int i = 0; i < cnt; i++) {
            int   r = __shfl_sync(0xFFFFFFFFu, sw.x, i);
            float w = __int_as_float(__shfl_sync(0xFFFFFFFFu, sw.y, i));
            float4 v = *(const float4*)(src + (size_t)r * DD + fo);
            ax += w * v.x; ay += w * v.y; az += w * v.z; aw += w * v.w;
        }
    }

    float4 b = *(const float4*)(bias + fo);
    ax = fmaxf(ax + b.x, 0.f);
    ay = fmaxf(ay + b.y, 0.f);
    az = fmaxf(az + b.z, 0.f);
    aw = fmaxf(aw + b.w, 0.f);
    if (RESID) {
        float4 rv = *(const float4*)(resid + (size_t)n * DD + fo);
        ax += rv.x; ay += rv.y; az += rv.z; aw += rv.w;
    }
    *(float4*)(dst + (size_t)n * DD + fo) = make_float4(ax, ay, az, aw);
}

// ---------------------------------------------------------------------------
extern "C" void kernel_launch(void* const* d_in, const int* in_sizes, int n_in,
                              void* d_out, int out_size) {
    const float* x   = (const float*)d_in[0];
    const int*   adj = (const int*)d_in[1];     // int32 [2, E]
    const float* ew  = (const float*)d_in[2];
    const float* W1  = (const float*)d_in[3];
    const float* b1  = (const float*)d_in[4];
    const float* W2  = (const float*)d_in[5];
    const float* b2  = (const float*)d_in[6];
    float*       out = (float*)d_out;

    const int E = in_sizes[2];           // 600000
    const int N = in_sizes[0] / DD;      // 50000

    // REAL device addresses of the scratch symbols. Passing the symbol name
    // itself from host code passes the host shadow address (ATS-served at
    // 200 GB/s over C2C — the 3.6 ms bug).
    float* tmp1 = nullptr;
    float* tmp2 = nullptr;
    cudaGetSymbolAddress((void**)&tmp1, g_tmp1);
    cudaGetSymbolAddress((void**)&tmp2, g_tmp2);

    const int TB = 256;
    dim3 blkE((E + TB - 1) / TB);
    dim3 blkN((N + TB - 1) / TB);
    dim3 blkW((N * 32 + TB - 1) / TB);   // warp-per-node
    dim3 blkG((N + 63) / 64);

    // Launch order keeps gemm1 in the profiled (4th) slot.
    zero_kernel<<<blkN, TB>>>(N);                        // 1
    count_kernel<<<blkE, TB>>>(adj, ew, E, N);           // 2
    scan_kernel<<<1, 1024>>>(N);                         // 3
    gemm_kernel<<<blkG, TB>>>(x, W1, tmp1, N);           // 4  <- profiled
    fill_kernel<<<blkE, TB>>>(adj, ew, E, N);            // 5

    // Layer 1 aggregate: tmp2 = relu(gather(tmp1) + b1)
    gather_kernel<false><<<blkW, TB>>>(tmp1, b1, nullptr, tmp2, N);  // 6

    // Layer 2: tmp1 = tmp2@W2 ; out = relu(gather(tmp1) + b2) + x
    gemm_kernel<<<blkG, TB>>>(tmp2, W2, tmp1, N);                    // 7
    gather_kernel<true><<<blkW, TB>>>(tmp1, b2, x, out, N);          // 8
}